// round 14
// baseline (speedup 1.0000x reference)
#include <cuda_runtime.h>
#include <cuda_bf16.h>
#include <cuda_fp8.h>
#include <cstdint>
#include <cstddef>

#define NT     8192
#define XLD    259
#define NTILES 64           // 4096 keys per CTA half / 64 per tile

// ---------------- device globals ----------------
__device__ unsigned char g_Qf8[NT * 256];
__device__ unsigned char g_Kf8[NT * 256];
__device__ unsigned char g_Vf8t[256 * NT];   // V transposed: [dim][token], e4m3
__device__ float4        g_pos4[NT];         // px,py,pz,|p|^2
__device__ float         g_Opart[2 * NT * 256];
__device__ float         g_spart[2 * NT];
__device__ float         g_mpart[2 * NT];

// ---------------- PTX helpers (base ISA only) ----------------
__device__ __forceinline__ uint32_t smem_u32(const void* p) {
    uint32_t a;
    asm("{ .reg .u64 t; cvta.to.shared.u64 t, %1; cvt.u32.u64 %0, t; }" : "=r"(a) : "l"(p));
    return a;
}
#define CP_COMMIT() asm volatile("cp.async.commit_group;" ::: "memory")
#define CP_WAIT0()  asm volatile("cp.async.wait_group 0;" ::: "memory")
__device__ __forceinline__ void cp16(uint32_t dst, const void* src) {
    asm volatile("cp.async.cg.shared.global [%0], [%1], 16;" :: "r"(dst), "l"(src));
}
__device__ __forceinline__ void ldsm4(uint32_t addr, uint32_t& r0, uint32_t& r1, uint32_t& r2, uint32_t& r3) {
    asm volatile("ldmatrix.sync.aligned.m8n8.x4.shared.b16 {%0,%1,%2,%3}, [%4];"
        : "=r"(r0), "=r"(r1), "=r"(r2), "=r"(r3) : "r"(addr));
}
// fp8 e4m3 MMA: m16n8k32, fp32 accum (sm_89+ base feature)
__device__ __forceinline__ void mma_fp8(float& c0, float& c1, float& c2, float& c3,
                                        uint32_t a0, uint32_t a1, uint32_t a2, uint32_t a3,
                                        uint32_t b0, uint32_t b1) {
    asm volatile("mma.sync.aligned.m16n8k32.row.col.f32.e4m3.e4m3.f32 "
        "{%0,%1,%2,%3}, {%4,%5,%6,%7}, {%8,%9}, {%0,%1,%2,%3};"
        : "+f"(c0), "+f"(c1), "+f"(c2), "+f"(c3)
        : "r"(a0), "r"(a1), "r"(a2), "r"(a3), "r"(b0), "r"(b1));
}
#define SWZ(x) ((x) ^ (((x) >> 3) & 0x70))

// ---------------- SMEM layout (attn) ----------------
#define SM_POS  0          // 2 x 1024
#define SM_P    2048       // 16384: 128 rows x 128B stride (64B used), e4m3
#define SM_Q    18432      // 32768: 2 fb-blocks x 128 rows x 128B
#define SM_K    51200      // 2 x 16384: per buf 2 fb-blocks x 64 keys x 128B
#define SM_V    83968      // 2 x 32768: per buf 256 dims x 128B stride (64B used)
#define SM_RED  149504     // 2048: red_m[2][128], red_s[2][128]
#define ATTN_SMEM 151552

// ---------------------------------------------------------------------------
// QKV GEMM (SIMT fp32) -> e4m3; V stored transposed.
// ---------------------------------------------------------------------------
__device__ __forceinline__ float f4get(float4 v, int c) {
    return (c == 0) ? v.x : (c == 1) ? v.y : (c == 2) ? v.z : v.w;
}
__device__ __forceinline__ unsigned char to_f8(float x) {
    return (unsigned char)__nv_cvt_float_to_fp8(x, __NV_SATFINITE, __NV_E4M3);
}

__global__ __launch_bounds__(256)
void qkv_kernel(const float* __restrict__ X,
                const float* __restrict__ WQ, const float* __restrict__ bQ,
                const float* __restrict__ WK, const float* __restrict__ bK,
                const float* __restrict__ WV, const float* __restrict__ bV)
{
    const float* W; const float* bias;
    if (blockIdx.z == 0)      { W = WQ; bias = bQ; }
    else if (blockIdx.z == 1) { W = WK; bias = bK; }
    else                      { W = WV; bias = bV; }

    __shared__ float Xs[64][68];
    __shared__ float Ws[64][64];

    const int tid = threadIdx.x;
    const int ty = tid >> 4, tx = tid & 15;
    const int m0 = blockIdx.x * 64, n0 = blockIdx.y * 64;

    float acc[4][4] = {};

    for (int k0 = 0; k0 < 256; k0 += 64) {
        #pragma unroll
        for (int i = 0; i < 16; i++) {
            int idx = tid + i * 256;
            int r = idx >> 6, c = idx & 63;
            Xs[r][c] = X[(m0 + r) * XLD + (k0 + c)];
        }
        #pragma unroll
        for (int i = 0; i < 4; i++) {
            int idx = tid + i * 256;
            int r = idx >> 4, c4 = (idx & 15) << 2;
            *(float4*)&Ws[r][c4] = *(const float4*)&W[(k0 + r) * 256 + (n0 + c4)];
        }
        __syncthreads();
        #pragma unroll 4
        for (int k = 0; k < 64; k += 4) {
            float4 xv[4];
            #pragma unroll
            for (int i = 0; i < 4; i++) xv[i] = *(const float4*)&Xs[ty * 4 + i][k];
            #pragma unroll
            for (int kk = 0; kk < 4; kk++) {
                float wv[4];
                #pragma unroll
                for (int j = 0; j < 4; j++) wv[j] = Ws[k + kk][tx + 16 * j];
                #pragma unroll
                for (int i = 0; i < 4; i++) {
                    float xs = f4get(xv[i], kk);
                    #pragma unroll
                    for (int j = 0; j < 4; j++) acc[i][j] += xs * wv[j];
                }
            }
        }
        __syncthreads();
    }

    if (blockIdx.z == 2) {
        #pragma unroll
        for (int j = 0; j < 4; j++) {
            int n = n0 + tx + 16 * j;
            float bv = bias[n];
            #pragma unroll
            for (int i = 0; i < 4; i++)
                g_Vf8t[(size_t)n * NT + (m0 + ty * 4 + i)] = to_f8(acc[i][j] + bv);
        }
    } else {
        unsigned char* C = (blockIdx.z == 0) ? g_Qf8 : g_Kf8;
        #pragma unroll
        for (int j = 0; j < 4; j++) {
            int n = n0 + tx + 16 * j;
            float bv = bias[n];
            #pragma unroll
            for (int i = 0; i < 4; i++)
                C[(size_t)(m0 + ty * 4 + i) * 256 + n] = to_f8(acc[i][j] + bv);
        }
    }
}

__global__ void pos_kernel(const float* __restrict__ X)
{
    int i = blockIdx.x * 256 + threadIdx.x;
    float x = X[(size_t)i * XLD + 256];
    float y = X[(size_t)i * XLD + 257];
    float z = X[(size_t)i * XLD + 258];
    g_pos4[i] = make_float4(x, y, z, x * x + y * y + z * z);
}

// ---------------- tile loaders (cp.async, SW128-swizzled, 512 threads) ----------------
__device__ __forceinline__ void load_k(uint32_t sb, int tid, int j0, int buf) {
    uint32_t kb = sb + SM_K + (uint32_t)buf * 16384u;
    #pragma unroll
    for (int i = 0; i < 2; i++) {
        int e = i * 512 + tid;               // 0..1023
        int key = e >> 4, q = e & 15;        // 16 x 16B chunks per 256B key row
        int fb = q >> 3, f = q & 7;
        uint32_t off = (uint32_t)(fb * 8192 + SWZ(key * 128 + f * 16));
        cp16(kb + off, g_Kf8 + ((size_t)(j0 + key)) * 256 + fb * 128 + f * 16);
    }
}
__device__ __forceinline__ void load_v(uint32_t sb, int tid, int j0, int buf) {
    uint32_t vb = sb + SM_V + (uint32_t)buf * 32768u;
    #pragma unroll
    for (int i = 0; i < 2; i++) {
        int e = i * 512 + tid;               // 0..1023
        int dim = e >> 2, q = e & 3;         // 4 x 16B chunks per 64B dim row
        uint32_t off = (uint32_t)SWZ(dim * 128 + q * 16);
        cp16(vb + off, g_Vf8t + ((size_t)dim) * NT + j0 + q * 16);
    }
}
__device__ __forceinline__ void load_pos(uint32_t sb, int tid, int j0, int buf) {
    if (tid < 64) cp16(sb + SM_POS + (uint32_t)buf * 1024u + tid * 16u, &g_pos4[j0 + tid]);
}

__device__ __forceinline__ float softel(float s, float4 q, float4 k, float& rmx) {
    float dot = fmaf(q.z, k.z, fmaf(q.y, k.y, q.x * k.x));
    float d2 = fmaxf(fmaf(-2.f, dot, q.w + k.w), 0.f);
    float x = s * 0.0625f * __expf(-0.5f * d2);
    rmx = fmaxf(rmx, x);
    return __expf(x);
}

// ---------------------------------------------------------------------------
// FP8 HMMA flash attention, 512 threads / 16 warps.
// S phase : warp = (rb = w&7 -> 16 rows, db = w>>3 -> 32 keys), k=256 feats (8 ksteps)
// PV phase: warp = (rb2 = w&3 -> 32 rows, db2 = w>>2 -> 64 dims), k=64 keys (2 ksteps)
// Unshifted exp: p=exp(x), m scalar max, O never rescaled; merge divides.
// ---------------------------------------------------------------------------
__global__ __launch_bounds__(512, 1)
void attn_kernel()
{
    extern __shared__ char smem[];
    const uint32_t sb = smem_u32(smem);
    const int tid = threadIdx.x;
    const int w = tid >> 5, l = tid & 31;
    const int rb = w & 7, db = w >> 3;
    const int rb2 = w & 3, db2 = w >> 2;
    const int g = l >> 2, t = l & 3;
    const int qb = blockIdx.x >> 1, half = blockIdx.x & 1;
    const int m0 = qb * 128, j0b = half * 4096;

    // ---- Q -> smem (once, e4m3), K/V/pos tile 0 ----
    #pragma unroll
    for (int i = 0; i < 4; i++) {
        int e = i * 512 + tid;               // 0..2047
        int row = e >> 4, q = e & 15;
        int fb = q >> 3, f = q & 7;
        uint32_t off = (uint32_t)(fb * 16384 + SWZ(row * 128 + f * 16));
        cp16(sb + SM_Q + off, g_Qf8 + ((size_t)(m0 + row)) * 256 + fb * 128 + f * 16);
    }
    load_k(sb, tid, j0b, 0);
    load_v(sb, tid, j0b, 0);
    load_pos(sb, tid, j0b, 0);
    CP_COMMIT();

    const float4 qpa = g_pos4[m0 + 16 * rb + g];
    const float4 qpb = g_pos4[m0 + 16 * rb + g + 8];

    float O[16][4];                           // [mr*8+on][4]: rows 32rb2+16mr+{g,g+8}, col 64db2+8on+2t
    #pragma unroll
    for (int n = 0; n < 16; n++) { O[n][0] = O[n][1] = O[n][2] = O[n][3] = 0.f; }
    float rmax0 = -1e30f, rmax1 = -1e30f, rsum0 = 0.f, rsum1 = 0.f;

    // ldmatrix lane address components
    const int lrow16 = l & 15;                 // A-pattern: m0 rows0-7, m1 rows8-15, m2/m3 = +16B
    const int lkh    = l >> 4;
    const int lr8    = (l & 7) + (l >> 4) * 8; // B-pattern: m0 r0-7 h0, m1 r0-7 h1, m2 r8-15 h0, m3 r8-15 h1
    const int lbh    = (l >> 3) & 1;

    for (int tt = 0; tt < NTILES; tt++) {
        const int buf = tt & 1;
        CP_WAIT0();
        __syncthreads();                      // KV(tt) visible; PV(tt-1) complete everywhere
        if (tt < NTILES - 1) {
            load_k(sb, tid, j0b + (tt + 1) * 64, (tt + 1) & 1);
            load_v(sb, tid, j0b + (tt + 1) * 64, (tt + 1) & 1);
            load_pos(sb, tid, j0b + (tt + 1) * 64, (tt + 1) & 1);
            CP_COMMIT();
        }

        // ---- S = Q K^T : rows 16rb..+15 x keys 32db..+31, 8 ksteps of 32 feats ----
        float S[4][4];
        #pragma unroll
        for (int n = 0; n < 4; n++) { S[n][0] = S[n][1] = S[n][2] = S[n][3] = 0.f; }
        const uint32_t kbase = sb + SM_K + (uint32_t)buf * 16384u;

        #pragma unroll
        for (int ks = 0; ks < 8; ks++) {
            const int fb = ks >> 2, inner = (ks & 3) * 32;
            uint32_t a0, a1, a2, a3;
            ldsm4(sb + SM_Q + fb * 16384 + SWZ((16 * rb + lrow16) * 128 + inner + lkh * 16),
                  a0, a1, a2, a3);
            #pragma unroll
            for (int jj = 0; jj < 2; jj++) {
                uint32_t b0, b1, b2, b3;   // (keys jj*16+0-7: b0,b1) (keys +8-15: b2,b3)
                ldsm4(kbase + fb * 8192 + SWZ((32 * db + 16 * jj + lr8) * 128 + inner + lbh * 16),
                      b0, b1, b2, b3);
                mma_fp8(S[2*jj][0], S[2*jj][1], S[2*jj][2], S[2*jj][3], a0, a1, a2, a3, b0, b1);
                mma_fp8(S[2*jj+1][0], S[2*jj+1][1], S[2*jj+1][2], S[2*jj+1][3], a0, a1, a2, a3, b2, b3);
            }
        }

        // ---- softmax + decay -> P smem (e4m3) ----
        const char* posb = smem + SM_POS + buf * 1024;
        #pragma unroll
        for (int nt = 0; nt < 4; nt++) {
            int c0 = db * 32 + 8 * nt + 2 * t;
            float4 k0 = *(const float4*)(posb + c0 * 16);
            float4 k1 = *(const float4*)(posb + c0 * 16 + 16);
            float p00 = softel(S[nt][0], qpa, k0, rmax0);
            float p01 = softel(S[nt][1], qpa, k1, rmax0);
            float p10 = softel(S[nt][2], qpb, k0, rmax1);
            float p11 = softel(S[nt][3], qpb, k1, rmax1);
            rsum0 += p00 + p01;
            rsum1 += p10 + p11;
            uint16_t h0 = (uint16_t)__nv_cvt_float2_to_fp8x2(make_float2(p00, p01), __NV_SATFINITE, __NV_E4M3);
            uint16_t h1 = (uint16_t)__nv_cvt_float2_to_fp8x2(make_float2(p10, p11), __NV_SATFINITE, __NV_E4M3);
            *(uint16_t*)(smem + SM_P + SWZ((16 * rb + g) * 128 + c0)) = h0;
            *(uint16_t*)(smem + SM_P + SWZ((16 * rb + g + 8) * 128 + c0)) = h1;
        }
        __syncthreads();   // P complete

        // ---- O += P V : rows 32rb2..+31 x dims 64db2..+63, 2 ksteps of 32 keys ----
        const uint32_t vbase = sb + SM_V + (uint32_t)buf * 32768u;
        #pragma unroll
        for (int kp = 0; kp < 2; kp++) {
            const int inner = kp * 32;
            uint32_t pa[2][4];
            #pragma unroll
            for (int mr = 0; mr < 2; mr++)
                ldsm4(sb + SM_P + SWZ((32 * rb2 + 16 * mr + lrow16) * 128 + inner + lkh * 16),
                      pa[mr][0], pa[mr][1], pa[mr][2], pa[mr][3]);
            #pragma unroll
            for (int dg = 0; dg < 4; dg++) {
                uint32_t b0, b1, b2, b3;   // (dims dg*16+0-7: b0,b1) (dims +8-15: b2,b3)
                ldsm4(vbase + SWZ((64 * db2 + 16 * dg + lr8) * 128 + inner + lbh * 16),
                      b0, b1, b2, b3);
                #pragma unroll
                for (int mr = 0; mr < 2; mr++) {
                    mma_fp8(O[mr*8+2*dg][0], O[mr*8+2*dg][1], O[mr*8+2*dg][2], O[mr*8+2*dg][3],
                            pa[mr][0], pa[mr][1], pa[mr][2], pa[mr][3], b0, b1);
                    mma_fp8(O[mr*8+2*dg+1][0], O[mr*8+2*dg+1][1], O[mr*8+2*dg+1][2], O[mr*8+2*dg+1][3],
                            pa[mr][0], pa[mr][1], pa[mr][2], pa[mr][3], b2, b3);
                }
            }
        }
        // no trailing barrier: loop-top sync covers P/KV reuse
    }

    // ---- row stats: quad-reduce, then cross-db via smem ----
    #pragma unroll
    for (int off = 1; off <= 2; off <<= 1) {
        rmax0 = fmaxf(rmax0, __shfl_xor_sync(0xffffffffu, rmax0, off));
        rmax1 = fmaxf(rmax1, __shfl_xor_sync(0xffffffffu, rmax1, off));
        rsum0 += __shfl_xor_sync(0xffffffffu, rsum0, off);
        rsum1 += __shfl_xor_sync(0xffffffffu, rsum1, off);
    }
    float* red_m = (float*)(smem + SM_RED);          // [2][128]
    float* red_s = (float*)(smem + SM_RED + 1024);   // [2][128]
    __syncthreads();
    if (t == 0) {
        red_m[db * 128 + 16 * rb + g]     = rmax0;
        red_m[db * 128 + 16 * rb + g + 8] = rmax1;
        red_s[db * 128 + 16 * rb + g]     = rsum0;
        red_s[db * 128 + 16 * rb + g + 8] = rsum1;
    }
    __syncthreads();
    if (tid < 128) {
        g_mpart[half * NT + m0 + tid] = fmaxf(red_m[tid], red_m[128 + tid]);
        g_spart[half * NT + m0 + tid] = red_s[tid] + red_s[128 + tid];
    }

    // ---- O writeback (fp32 partials) ----
    float* ob = &g_Opart[(size_t)half * NT * 256];
    #pragma unroll
    for (int mr = 0; mr < 2; mr++) {
        int row0 = m0 + 32 * rb2 + 16 * mr + g;
        #pragma unroll
        for (int on = 0; on < 8; on++) {
            int col = 64 * db2 + 8 * on + 2 * t;
            *(float2*)&ob[(size_t)row0 * 256 + col]       = make_float2(O[mr*8+on][0], O[mr*8+on][1]);
            *(float2*)&ob[(size_t)(row0 + 8) * 256 + col] = make_float2(O[mr*8+on][2], O[mr*8+on][3]);
        }
    }
}

// ---------------------------------------------------------------------------
// merge: H = (O0+O1)/(exp(max(m0,m1)) + s0 + s1) + Xf
// ---------------------------------------------------------------------------
__global__ __launch_bounds__(256)
void merge_kernel(const float* __restrict__ X, float* __restrict__ out)
{
    int r = blockIdx.x * 4 + (threadIdx.x >> 6);
    int c = (threadIdx.x & 63) * 4;
    float m = fmaxf(g_mpart[r], g_mpart[NT + r]);
    float d = 1.f / (__expf(m) + g_spart[r] + g_spart[NT + r]);
    float4 o0 = *(const float4*)&g_Opart[(size_t)r * 256 + c];
    float4 o1 = *(const float4*)&g_Opart[(size_t)NT * 256 + (size_t)r * 256 + c];
    const float* xr = &X[(size_t)r * XLD + c];
    float4 o;
    o.x = (o0.x + o1.x) * d + xr[0];
    o.y = (o0.y + o1.y) * d + xr[1];
    o.z = (o0.z + o1.z) * d + xr[2];
    o.w = (o0.w + o1.w) * d + xr[3];
    *(float4*)&out[(size_t)r * 256 + c] = o;
}

extern "C" void kernel_launch(void* const* d_in, const int* in_sizes, int n_in,
                              void* d_out, int out_size)
{
    const float* X  = (const float*)d_in[0];
    const float* WQ = (const float*)d_in[1];
    const float* bQ = (const float*)d_in[2];
    const float* WK = (const float*)d_in[3];
    const float* bK = (const float*)d_in[4];
    const float* WV = (const float*)d_in[5];
    const float* bV = (const float*)d_in[6];
    float* out = (float*)d_out;

    cudaFuncSetAttribute(attn_kernel, cudaFuncAttributeMaxDynamicSharedMemorySize, ATTN_SMEM);

    pos_kernel<<<NT / 256, 256>>>(X);
    dim3 g1(NT / 64, 4, 3);
    qkv_kernel<<<g1, 256>>>(X, WQ, bQ, WK, bK, WV, bV);
    attn_kernel<<<128, 512, ATTN_SMEM>>>();
    merge_kernel<<<NT / 4, 256>>>(X, out);
}

// round 16
// speedup vs baseline: 1.0891x; 1.0891x over previous
#include <cuda_runtime.h>
#include <cuda_bf16.h>
#include <cstdint>
#include <cstddef>

#define NT     8192
#define XLD    259
#define NTILES 64           // 4096 keys per CTA half / 64 per tile

// ---------------- device globals ----------------
__device__ __nv_bfloat16 g_Qb[NT * 256];
__device__ __nv_bfloat16 g_Kb[NT * 256];
__device__ __nv_bfloat16 g_Vt[256 * NT];     // V transposed: [dim][token]
__device__ float4        g_pos4[NT];         // px,py,pz,|p|^2
__device__ float         g_Opart[2 * NT * 256];
__device__ float         g_spart[2 * NT];
__device__ float         g_mpart[2 * NT];

// ---------------- PTX helpers (base ISA only) ----------------
__device__ __forceinline__ uint32_t smem_u32(const void* p) {
    uint32_t a;
    asm("{ .reg .u64 t; cvta.to.shared.u64 t, %1; cvt.u32.u64 %0, t; }" : "=r"(a) : "l"(p));
    return a;
}
#define CP_COMMIT() asm volatile("cp.async.commit_group;" ::: "memory")
#define CP_WAIT0()  asm volatile("cp.async.wait_group 0;" ::: "memory")
__device__ __forceinline__ void cp16(uint32_t dst, const void* src) {
    asm volatile("cp.async.cg.shared.global [%0], [%1], 16;" :: "r"(dst), "l"(src));
}
__device__ __forceinline__ void ldsm4(uint32_t addr, uint32_t& r0, uint32_t& r1, uint32_t& r2, uint32_t& r3) {
    asm volatile("ldmatrix.sync.aligned.m8n8.x4.shared.b16 {%0,%1,%2,%3}, [%4];"
        : "=r"(r0), "=r"(r1), "=r"(r2), "=r"(r3) : "r"(addr));
}
__device__ __forceinline__ void mma_bf16(float& c0, float& c1, float& c2, float& c3,
                                         uint32_t a0, uint32_t a1, uint32_t a2, uint32_t a3,
                                         uint32_t b0, uint32_t b1) {
    asm volatile("mma.sync.aligned.m16n8k16.row.col.f32.bf16.bf16.f32 "
        "{%0,%1,%2,%3}, {%4,%5,%6,%7}, {%8,%9}, {%0,%1,%2,%3};"
        : "+f"(c0), "+f"(c1), "+f"(c2), "+f"(c3)
        : "r"(a0), "r"(a1), "r"(a2), "r"(a3), "r"(b0), "r"(b1));
}
#define SWZ(x) ((x) ^ (((x) >> 3) & 0x70))

// ---------------- SMEM layout (attn) ----------------
#define SM_POS  0          // 2 x 1024 (reused as red_m/red_s at epilogue)
#define SM_P    2048       // 2 x 16384 (128 rows x 64 keys bf16, 128B rows)
#define SM_Q    34816      // 65536  (4 fb-blocks x 128 rows x 128B)
#define SM_K    100352     // 2 x 32768
#define SM_V    165888     // 2 x 32768
#define ATTN_SMEM 231424

// ---------------------------------------------------------------------------
// QKV GEMM (SIMT fp32) -> bf16; V stored transposed.
// ---------------------------------------------------------------------------
__device__ __forceinline__ float f4get(float4 v, int c) {
    return (c == 0) ? v.x : (c == 1) ? v.y : (c == 2) ? v.z : v.w;
}

__global__ __launch_bounds__(256)
void qkv_kernel(const float* __restrict__ X,
                const float* __restrict__ WQ, const float* __restrict__ bQ,
                const float* __restrict__ WK, const float* __restrict__ bK,
                const float* __restrict__ WV, const float* __restrict__ bV)
{
    const float* W; const float* bias;
    if (blockIdx.z == 0)      { W = WQ; bias = bQ; }
    else if (blockIdx.z == 1) { W = WK; bias = bK; }
    else                      { W = WV; bias = bV; }

    __shared__ float Xs[64][68];
    __shared__ float Ws[64][64];

    const int tid = threadIdx.x;
    const int ty = tid >> 4, tx = tid & 15;
    const int m0 = blockIdx.x * 64, n0 = blockIdx.y * 64;

    float acc[4][4] = {};

    for (int k0 = 0; k0 < 256; k0 += 64) {
        #pragma unroll
        for (int i = 0; i < 16; i++) {
            int idx = tid + i * 256;
            int r = idx >> 6, c = idx & 63;
            Xs[r][c] = X[(m0 + r) * XLD + (k0 + c)];
        }
        #pragma unroll
        for (int i = 0; i < 4; i++) {
            int idx = tid + i * 256;
            int r = idx >> 4, c4 = (idx & 15) << 2;
            *(float4*)&Ws[r][c4] = *(const float4*)&W[(k0 + r) * 256 + (n0 + c4)];
        }
        __syncthreads();
        #pragma unroll 4
        for (int k = 0; k < 64; k += 4) {
            float4 xv[4];
            #pragma unroll
            for (int i = 0; i < 4; i++) xv[i] = *(const float4*)&Xs[ty * 4 + i][k];
            #pragma unroll
            for (int kk = 0; kk < 4; kk++) {
                float wv[4];
                #pragma unroll
                for (int j = 0; j < 4; j++) wv[j] = Ws[k + kk][tx + 16 * j];
                #pragma unroll
                for (int i = 0; i < 4; i++) {
                    float xs = f4get(xv[i], kk);
                    #pragma unroll
                    for (int j = 0; j < 4; j++) acc[i][j] += xs * wv[j];
                }
            }
        }
        __syncthreads();
    }

    if (blockIdx.z == 2) {
        #pragma unroll
        for (int j = 0; j < 4; j++) {
            int n = n0 + tx + 16 * j;
            float bv = bias[n];
            #pragma unroll
            for (int i = 0; i < 4; i++)
                g_Vt[(size_t)n * NT + (m0 + ty * 4 + i)] = __float2bfloat16_rn(acc[i][j] + bv);
        }
    } else {
        __nv_bfloat16* C = (blockIdx.z == 0) ? g_Qb : g_Kb;
        #pragma unroll
        for (int j = 0; j < 4; j++) {
            int n = n0 + tx + 16 * j;
            float bv = bias[n];
            #pragma unroll
            for (int i = 0; i < 4; i++)
                C[(size_t)(m0 + ty * 4 + i) * 256 + n] = __float2bfloat16_rn(acc[i][j] + bv);
        }
    }
}

__global__ void pos_kernel(const float* __restrict__ X)
{
    int i = blockIdx.x * 256 + threadIdx.x;
    float x = X[(size_t)i * XLD + 256];
    float y = X[(size_t)i * XLD + 257];
    float z = X[(size_t)i * XLD + 258];
    g_pos4[i] = make_float4(x, y, z, x * x + y * y + z * z);
}

// ---------------- tile loaders (cp.async, SW128-swizzled, 512 threads) ----------------
__device__ __forceinline__ void load_k(uint32_t sb, int tid, int j0, int buf) {
    uint32_t kb = sb + SM_K + (uint32_t)buf * 32768u;
    #pragma unroll
    for (int i = 0; i < 4; i++) {
        int e = i * 512 + tid;               // 0..2047
        int key = e >> 5, q = e & 31;
        int fb = q >> 3, f8 = q & 7;
        uint32_t off = (uint32_t)(fb * 8192 + SWZ(key * 128 + f8 * 16));
        cp16(kb + off, (const char*)g_Kb + (((size_t)(j0 + key)) * 256 + fb * 64 + f8 * 8) * 2);
    }
}
__device__ __forceinline__ void load_v(uint32_t sb, int tid, int j0, int buf) {
    uint32_t vb = sb + SM_V + (uint32_t)buf * 32768u;
    #pragma unroll
    for (int i = 0; i < 4; i++) {
        int e = i * 512 + tid;
        int dim = e >> 3, q = e & 7;
        uint32_t off = (uint32_t)SWZ(dim * 128 + q * 16);
        cp16(vb + off, (const char*)g_Vt + (((size_t)dim) * NT + j0 + q * 8) * 2);
    }
}
__device__ __forceinline__ void load_pos(uint32_t sb, int tid, int j0, int buf) {
    if (tid < 64) cp16(sb + SM_POS + (uint32_t)buf * 1024u + tid * 16u, &g_pos4[j0 + tid]);
}

__device__ __forceinline__ float softel(float s, float4 q, float4 k, float& rmx) {
    float dot = fmaf(q.z, k.z, fmaf(q.y, k.y, q.x * k.x));
    float d2 = fmaxf(fmaf(-2.f, dot, q.w + k.w), 0.f);
    float x = s * 0.0625f * __expf(-0.5f * d2);
    rmx = fmaxf(rmx, x);
    return __expf(x);
}

// ---------------------------------------------------------------------------
// bf16 HMMA flash attention, 512 threads, software-pipelined PV(t-1).
// Region per tile: bar; S(t); softmax(t)->P[t&1]; PV(t-1); bar; prefetch(t+1).
// Softmax overlaps other warps' S/PV MMAs inside the region (warp skew).
// S phase : warp = (rb = w&7 -> 16 rows, db = w>>3 -> 32 keys)
// PV phase: warp = (rb2 = w&3 -> 32 rows, db2 = w>>2 -> 64 dims)
// Unshifted exp: p=exp(x), m scalar max, O never rescaled; merge divides.
// ---------------------------------------------------------------------------
__global__ __launch_bounds__(512, 1)
void attn_kernel()
{
    extern __shared__ char smem[];
    const uint32_t sb = smem_u32(smem);
    const int tid = threadIdx.x;
    const int w = tid >> 5, l = tid & 31;
    const int rb = w & 7, db = w >> 3;
    const int rb2 = w & 3, db2 = w >> 2;
    const int g = l >> 2, t = l & 3;
    const int qb = blockIdx.x >> 1, half = blockIdx.x & 1;
    const int m0 = qb * 128, j0b = half * 4096;

    // ---- Q -> smem (once), K/V/pos tiles 0 ----
    #pragma unroll
    for (int i = 0; i < 8; i++) {
        int e = i * 512 + tid;               // 0..4095
        int row = e >> 5, q = e & 31;
        int fb = q >> 3, f8 = q & 7;
        uint32_t off = (uint32_t)(fb * 16384 + SWZ(row * 128 + f8 * 16));
        cp16(sb + SM_Q + off, (const char*)g_Qb + (((size_t)(m0 + row)) * 256 + fb * 64 + f8 * 8) * 2);
    }
    load_k(sb, tid, j0b, 0);
    load_v(sb, tid, j0b, 0);
    load_pos(sb, tid, j0b, 0);
    CP_COMMIT();

    const float4 qpa = g_pos4[m0 + 16 * rb + g];
    const float4 qpb = g_pos4[m0 + 16 * rb + g + 8];

    float O[16][4];                           // [mr*8+on][4]: rows 32rb2+16mr+{g,g+8}, col 64db2+8on+2t
    #pragma unroll
    for (int n = 0; n < 16; n++) { O[n][0] = O[n][1] = O[n][2] = O[n][3] = 0.f; }
    float rmax0 = -1e30f, rmax1 = -1e30f, rsum0 = 0.f, rsum1 = 0.f;

    // ldmatrix lane address components
    const int lrow16 = l & 15;
    const int lkh    = l >> 4;
    const int lr8    = (l & 7) + (l >> 4) * 8;
    const int lbh    = (l >> 3) & 1;

    for (int tt = 0; tt < NTILES; tt++) {
        const int buf = tt & 1;
        CP_WAIT0();
        __syncthreads();                      // bar1: KV(tt) visible; P(tt-1) complete; prefetch slots free

        // ---- S = Q K^T : rows 16rb..+15 x keys 32db..+31, depth 256 ----
        float S[4][4];
        #pragma unroll
        for (int n = 0; n < 4; n++) { S[n][0] = S[n][1] = S[n][2] = S[n][3] = 0.f; }
        const uint32_t kbase = sb + SM_K + (uint32_t)buf * 32768u;

        #pragma unroll 8
        for (int ks = 0; ks < 16; ks++) {
            const int fb = ks >> 2, kc = (ks & 3) * 2;
            uint32_t a0, a1, a2, a3;
            ldsm4(sb + SM_Q + fb * 16384 + SWZ((16 * rb + lrow16) * 128 + (kc + lkh) * 16),
                  a0, a1, a2, a3);
            #pragma unroll
            for (int jj = 0; jj < 2; jj++) {
                uint32_t b0, b1, b2, b3;
                ldsm4(kbase + fb * 8192 + SWZ((db * 32 + 16 * jj + lr8) * 128 + (kc + lbh) * 16),
                      b0, b1, b2, b3);
                mma_bf16(S[2*jj][0], S[2*jj][1], S[2*jj][2], S[2*jj][3], a0, a1, a2, a3, b0, b1);
                mma_bf16(S[2*jj+1][0], S[2*jj+1][1], S[2*jj+1][2], S[2*jj+1][3], a0, a1, a2, a3, b2, b3);
            }
        }

        // ---- softmax + decay -> P[tt&1] (bf16) ----
        const char* posb = smem + SM_POS + buf * 1024;
        #pragma unroll
        for (int nt = 0; nt < 4; nt++) {
            int c0 = db * 32 + 8 * nt + 2 * t;
            float4 k0 = *(const float4*)(posb + c0 * 16);
            float4 k1 = *(const float4*)(posb + c0 * 16 + 16);
            float p00 = softel(S[nt][0], qpa, k0, rmax0);
            float p01 = softel(S[nt][1], qpa, k1, rmax0);
            float p10 = softel(S[nt][2], qpb, k0, rmax1);
            float p11 = softel(S[nt][3], qpb, k1, rmax1);
            rsum0 += p00 + p01;
            rsum1 += p10 + p11;
            __nv_bfloat162 h0 = __floats2bfloat162_rn(p00, p01);
            __nv_bfloat162 h1 = __floats2bfloat162_rn(p10, p11);
            *(uint32_t*)(smem + SM_P + buf * 16384 + SWZ((16 * rb + g) * 128 + c0 * 2)) = *(uint32_t*)&h0;
            *(uint32_t*)(smem + SM_P + buf * 16384 + SWZ((16 * rb + g + 8) * 128 + c0 * 2)) = *(uint32_t*)&h1;
        }

        // ---- O += P(tt-1) V(tt-1) : rows 32rb2..+31 x dims 64db2..+63 ----
        if (tt >= 1) {
            const int pb = (tt - 1) & 1;
            const uint32_t vbase = sb + SM_V + (uint32_t)pb * 32768u;
            const uint32_t pbase = sb + SM_P + (uint32_t)pb * 16384u;
            #pragma unroll
            for (int kp = 0; kp < 4; kp++) {
                uint32_t pa[2][4];
                #pragma unroll
                for (int mr = 0; mr < 2; mr++)
                    ldsm4(pbase + SWZ((32 * rb2 + 16 * mr + lrow16) * 128 + (2 * kp + lkh) * 16),
                          pa[mr][0], pa[mr][1], pa[mr][2], pa[mr][3]);
                #pragma unroll
                for (int dd = 0; dd < 4; dd++) {
                    uint32_t b0, b1, b2, b3;
                    ldsm4(vbase + SWZ((64 * db2 + 16 * dd + lr8) * 128 + (2 * kp + lbh) * 16),
                          b0, b1, b2, b3);
                    #pragma unroll
                    for (int mr = 0; mr < 2; mr++) {
                        mma_bf16(O[mr*8+2*dd][0], O[mr*8+2*dd][1], O[mr*8+2*dd][2], O[mr*8+2*dd][3],
                                 pa[mr][0], pa[mr][1], pa[mr][2], pa[mr][3], b0, b1);
                        mma_bf16(O[mr*8+2*dd+1][0], O[mr*8+2*dd+1][1], O[mr*8+2*dd+1][2], O[mr*8+2*dd+1][3],
                                 pa[mr][0], pa[mr][1], pa[mr][2], pa[mr][3], b2, b3);
                    }
                }
            }
        }

        __syncthreads();                      // bar2: all PV(tt-1) + softmax(tt) done
        if (tt < NTILES - 1) {
            load_k(sb, tid, j0b + (tt + 1) * 64, (tt + 1) & 1);
            load_v(sb, tid, j0b + (tt + 1) * 64, (tt + 1) & 1);
            load_pos(sb, tid, j0b + (tt + 1) * 64, (tt + 1) & 1);
            CP_COMMIT();
        }
    }

    // ---- final PV(NTILES-1) ----
    {
        const int pb = (NTILES - 1) & 1;
        const uint32_t vbase = sb + SM_V + (uint32_t)pb * 32768u;
        const uint32_t pbase = sb + SM_P + (uint32_t)pb * 16384u;
        #pragma unroll
        for (int kp = 0; kp < 4; kp++) {
            uint32_t pa[2][4];
            #pragma unroll
            for (int mr = 0; mr < 2; mr++)
                ldsm4(pbase + SWZ((32 * rb2 + 16 * mr + lrow16) * 128 + (2 * kp + lkh) * 16),
                      pa[mr][0], pa[mr][1], pa[mr][2], pa[mr][3]);
            #pragma unroll
            for (int dd = 0; dd < 4; dd++) {
                uint32_t b0, b1, b2, b3;
                ldsm4(vbase + SWZ((64 * db2 + 16 * dd + lr8) * 128 + (2 * kp + lbh) * 16),
                      b0, b1, b2, b3);
                #pragma unroll
                for (int mr = 0; mr < 2; mr++) {
                    mma_bf16(O[mr*8+2*dd][0], O[mr*8+2*dd][1], O[mr*8+2*dd][2], O[mr*8+2*dd][3],
                             pa[mr][0], pa[mr][1], pa[mr][2], pa[mr][3], b0, b1);
                    mma_bf16(O[mr*8+2*dd+1][0], O[mr*8+2*dd+1][1], O[mr*8+2*dd+1][2], O[mr*8+2*dd+1][3],
                             pa[mr][0], pa[mr][1], pa[mr][2], pa[mr][3], b2, b3);
                }
            }
        }
    }

    // ---- row stats: quad-reduce, then cross-db via smem (red aliases pos region) ----
    #pragma unroll
    for (int off = 1; off <= 2; off <<= 1) {
        rmax0 = fmaxf(rmax0, __shfl_xor_sync(0xffffffffu, rmax0, off));
        rmax1 = fmaxf(rmax1, __shfl_xor_sync(0xffffffffu, rmax1, off));
        rsum0 += __shfl_xor_sync(0xffffffffu, rsum0, off);
        rsum1 += __shfl_xor_sync(0xffffffffu, rsum1, off);
    }
    __syncthreads();                          // pos region free for reuse
    float* red_m = (float*)(smem + SM_POS);          // [2][128]
    float* red_s = (float*)(smem + SM_POS + 1024);   // [2][128]
    if (t == 0) {
        red_m[db * 128 + 16 * rb + g]     = rmax0;
        red_m[db * 128 + 16 * rb + g + 8] = rmax1;
        red_s[db * 128 + 16 * rb + g]     = rsum0;
        red_s[db * 128 + 16 * rb + g + 8] = rsum1;
    }
    __syncthreads();
    if (tid < 128) {
        g_mpart[half * NT + m0 + tid] = fmaxf(red_m[tid], red_m[128 + tid]);
        g_spart[half * NT + m0 + tid] = red_s[tid] + red_s[128 + tid];
    }

    // ---- O writeback (fp32 partials) ----
    float* ob = &g_Opart[(size_t)half * NT * 256];
    #pragma unroll
    for (int mr = 0; mr < 2; mr++) {
        int row0 = m0 + 32 * rb2 + 16 * mr + g;
        #pragma unroll
        for (int on = 0; on < 8; on++) {
            int col = 64 * db2 + 8 * on + 2 * t;
            *(float2*)&ob[(size_t)row0 * 256 + col]       = make_float2(O[mr*8+on][0], O[mr*8+on][1]);
            *(float2*)&ob[(size_t)(row0 + 8) * 256 + col] = make_float2(O[mr*8+on][2], O[mr*8+on][3]);
        }
    }
}

// ---------------------------------------------------------------------------
// merge: H = (O0+O1)/(exp(max(m0,m1)) + s0 + s1) + Xf
// ---------------------------------------------------------------------------
__global__ __launch_bounds__(256)
void merge_kernel(const float* __restrict__ X, float* __restrict__ out)
{
    int r = blockIdx.x * 4 + (threadIdx.x >> 6);
    int c = (threadIdx.x & 63) * 4;
    float m = fmaxf(g_mpart[r], g_mpart[NT + r]);
    float d = 1.f / (__expf(m) + g_spart[r] + g_spart[NT + r]);
    float4 o0 = *(const float4*)&g_Opart[(size_t)r * 256 + c];
    float4 o1 = *(const float4*)&g_Opart[(size_t)NT * 256 + (size_t)r * 256 + c];
    const float* xr = &X[(size_t)r * XLD + c];
    float4 o;
    o.x = (o0.x + o1.x) * d + xr[0];
    o.y = (o0.y + o1.y) * d + xr[1];
    o.z = (o0.z + o1.z) * d + xr[2];
    o.w = (o0.w + o1.w) * d + xr[3];
    *(float4*)&out[(size_t)r * 256 + c] = o;
}

extern "C" void kernel_launch(void* const* d_in, const int* in_sizes, int n_in,
                              void* d_out, int out_size)
{
    const float* X  = (const float*)d_in[0];
    const float* WQ = (const float*)d_in[1];
    const float* bQ = (const float*)d_in[2];
    const float* WK = (const float*)d_in[3];
    const float* bK = (const float*)d_in[4];
    const float* WV = (const float*)d_in[5];
    const float* bV = (const float*)d_in[6];
    float* out = (float*)d_out;

    cudaFuncSetAttribute(attn_kernel, cudaFuncAttributeMaxDynamicSharedMemorySize, ATTN_SMEM);

    pos_kernel<<<NT / 256, 256>>>(X);
    dim3 g1(NT / 64, 4, 3);
    qkv_kernel<<<g1, 256>>>(X, WQ, bQ, WK, bK, WV, bV);
    attn_kernel<<<128, 512, ATTN_SMEM>>>();
    merge_kernel<<<NT / 4, 256>>>(X, out);
}